// round 12
// baseline (speedup 1.0000x reference)
#include <cuda_runtime.h>
#include <cuda_fp16.h>
#include <math.h>
#include <stdint.h>

// Problem constants: B=64, N=1024, D=8, S=16 -> DS=128, K=1024
#define NN    1024
#define BB    64
#define DS    128
#define KDIM  1024
#define NKB   (KDIM / 16)            // 64 k16-blocks
#define NSTG  8                      // pipeline stages
#define STGB  8192                   // bytes per stage: A 4KB + B 4KB (frag order)
#define C_STRIDE 129
#define SMEM_REQ (128 * C_STRIDE * 4 + 1024)   // 67072 (covers 1024 + 8*8192 = 66560)

__device__ __forceinline__ uint32_t smem_u32(const void* p) {
    uint32_t a;
    asm("{ .reg .u64 t; cvta.to.shared.u64 t, %1; cvt.u32.u64 %0, t; }" : "=r"(a) : "l"(p));
    return a;
}
__device__ __forceinline__ void cp16(uint32_t dst, const void* src) {
    asm volatile("cp.async.cg.shared.global [%0], [%1], 16;" :: "r"(dst), "l"(src) : "memory");
}
__device__ __forceinline__ void mma16816(float* c, const uint32_t* a, uint32_t b0, uint32_t b1) {
    asm volatile("mma.sync.aligned.m16n8k16.row.col.f32.f16.f16.f32 "
                 "{%0,%1,%2,%3}, {%4,%5,%6,%7}, {%8,%9}, {%0,%1,%2,%3};"
                 : "+f"(c[0]), "+f"(c[1]), "+f"(c[2]), "+f"(c[3])
                 : "r"(a[0]), "r"(a[1]), "r"(a[2]), "r"(a[3]), "r"(b0), "r"(b1));
}

#define MB_INIT(mbar, cnt) \
    asm volatile("mbarrier.init.shared.b64 [%0], %1;" :: "r"(mbar), "r"((uint32_t)(cnt)) : "memory")
#define MB_ARRIVE(mbar) \
    asm volatile("mbarrier.arrive.shared.b64 _, [%0];" :: "r"(mbar) : "memory")
// .noinc is load-bearing: without it each call bumps the pending count first
// (net-zero progress) and the barrier never completes -> R11 deadlock.
#define CP_MB_ARRIVE(mbar) \
    asm volatile("cp.async.mbarrier.arrive.noinc.shared::cta.b64 [%0];" :: "r"(mbar) : "memory")
#define MB_WAIT(mbar, par) do {                                                \
    uint32_t _m = (mbar); uint32_t _p = (uint32_t)(par);                       \
    asm volatile("{\n\t.reg .pred P1;\n\t"                                     \
        "WL_%=:\n\t"                                                           \
        "mbarrier.try_wait.parity.acquire.cta.shared::cta.b64 P1, [%0], %1, 0x989680;\n\t" \
        "@P1 bra.uni WD_%=;\n\t"                                               \
        "bra.uni WL_%=;\n\t"                                                   \
        "WD_%=:\n\t}"                                                          \
        :: "r"(_m), "r"(_p) : "memory");                                       \
} while (0)

// ---------------- device scratch: FRAGMENT-ORDERED operands ----------------
// A frags: [row16 0..63][kb 0..63][lane 0..31][4 u32]   (2 MB)
// B frags: [b*8 + n16][kb][lane][4 u32]                (16 MB)
__device__ uint32_t g_Af[64 * NKB * 128];
__device__ uint32_t g_Xf[BB * 8 * NKB * 128];

// ---------------- prep: build fragment-ordered A and B (proven R10) --------
__global__ void prep(const float* __restrict__ x, const float* __restrict__ M)
{
    const int tid = threadIdx.x;
    const int kb  = blockIdx.x;

    if (tid < 128) {
        const int row16 = blockIdx.y;
        const int lane = tid >> 2, reg = tid & 3;
        const int R = row16 * 16 + (lane >> 2) + (reg & 1) * 8;
        const int C = kb * 16 + (lane & 3) * 2 + ((reg >> 1) & 1) * 8;
        const float2 mv = *(const float2*)&M[(size_t)R * NN + C];
        const __half2 h = __floats2half2_rn(mv.x, mv.y);
        g_Af[((size_t)row16 * NKB + kb) * 128 + tid] = *(const uint32_t*)&h;
    }

    __shared__ float sx[16 * 132];
    const int b = blockIdx.y;
    const float* src = x + ((size_t)b * NN + kb * 16) * DS;
#pragma unroll
    for (int j = tid; j < 16 * 128; j += 256) {
        const int r = j >> 7, c = j & 127;
        sx[r * 132 + c] = src[r * DS + c];
    }
    __syncthreads();

    uint32_t* dstB = g_Xf + ((size_t)(b * 8) * NKB + kb) * 128;
#pragma unroll
    for (int it = 0; it < 4; it++) {
        const int u = it * 256 + tid;
        const int n16 = u >> 7, tt = u & 127;
        const int lane = tt >> 2, reg = tt & 3;
        const int n  = n16 * 16 + (lane >> 2) + ((reg >> 1) & 1) * 8;
        const int k0 = (lane & 3) * 2 + (reg & 1) * 8;
        const __half2 h = __floats2half2_rn(sx[k0 * 132 + n], sx[(k0 + 1) * 132 + n]);
        dstB[(size_t)n16 * (NKB * 128) + tt] = *(const uint32_t*)&h;
    }
}

// ---------------- GEMM: 8-stage mbarrier cp.async pipeline -----------------
// Grid (8, 64). Block 256 = 8 warps (2 m x 4 n), warp m64n32.
// smem: [0:128) mbarriers (full[s]@s*16, empty[s]@s*16+8); stages at 1024.
__global__ void __launch_bounds__(256, 2) gemm_neuron(
    const float* __restrict__ w_syn,    // [N, 128]
    const float* __restrict__ b_dend,   // [N, 8]
    const float* __restrict__ w_dend,   // [N, 8]
    const float* __restrict__ b_soma,   // [N]
    float* __restrict__ out)            // [B, N]
{
    extern __shared__ char smem[];
    const uint32_t sb = smem_u32(smem);
    const int tid  = threadIdx.x;
    const int wid  = tid >> 5, lane = tid & 31;
    const int wm   = wid & 1;           // m-warp: 64 rows
    const int wn   = wid >> 1;          // n-warp: 32 cols
    const int o0   = blockIdx.x * 128;
    const int b    = blockIdx.y;

    if (tid == 0) {
#pragma unroll
        for (int s = 0; s < NSTG; s++) {
            MB_INIT(sb + s * 16,     256);   // full
            MB_INIT(sb + s * 16 + 8, 256);   // empty
        }
    }
    __syncthreads();

    // staging role: threads 0..127 -> A tile (tt>>4), 128..255 -> B tile
    const int  isA = (tid < 128);
    const int  tt  = isA ? tid : tid - 128;
    const int  tile = isA ? (blockIdx.x * 8 + (tt >> 4)) : (b * 8 + (tt >> 4));
    const uint32_t* srcbase = (isA ? g_Af : g_Xf)
                            + ((size_t)tile * NKB) * 128 + (tt & 15) * 8;
    const uint32_t dstoff = 1024 + (isA ? 0 : 4096) + (tt >> 4) * 512 + (tt & 15) * 32;

#define STAGE(j, dowait) do {                                              \
    const int _s = (j) & (NSTG - 1);                                       \
    if (dowait) MB_WAIT(sb + _s * 16 + 8, (((j) >> 3) + 1) & 1);           \
    const uint32_t _d = sb + dstoff + _s * STGB;                           \
    const uint32_t* _src = srcbase + (size_t)(j) * 128;                    \
    cp16(_d,      _src);                                                   \
    cp16(_d + 16, _src + 4);                                               \
    CP_MB_ARRIVE(sb + _s * 16);                                            \
} while (0)

    // prologue: fill 7 stages (no waits needed, buffers virgin)
#pragma unroll
    for (int j = 0; j < NSTG - 1; j++) STAGE(j, false);

    float acc[4][4][4];
#pragma unroll
    for (int mt = 0; mt < 4; mt++)
#pragma unroll
        for (int nt = 0; nt < 4; nt++)
#pragma unroll
            for (int q = 0; q < 4; q++) acc[mt][nt][q] = 0.f;

    const uint32_t aoff = 1024 + wm * 4 * 512 + lane * 16;
    const uint32_t boff = 1024 + 4096 + wn * 2 * 512 + lane * 16;

#pragma unroll 2
    for (int kb = 0; kb < NKB; kb++) {
        if (kb + NSTG - 1 < NKB) STAGE(kb + NSTG - 1, true);

        const int s = kb & (NSTG - 1);
        MB_WAIT(sb + s * 16, (kb >> 3) & 1);

        const char* stg = smem + s * STGB;
        uint4 Af[4], Bf[2];
#pragma unroll
        for (int mt = 0; mt < 4; mt++)
            Af[mt] = *(const uint4*)(stg + aoff + mt * 512);
#pragma unroll
        for (int bt = 0; bt < 2; bt++)
            Bf[bt] = *(const uint4*)(stg + boff + bt * 512);

#pragma unroll
        for (int mt = 0; mt < 4; mt++)
#pragma unroll
            for (int bt = 0; bt < 2; bt++) {
                mma16816(acc[mt][bt * 2],     (const uint32_t*)&Af[mt], Bf[bt].x, Bf[bt].y);
                mma16816(acc[mt][bt * 2 + 1], (const uint32_t*)&Af[mt], Bf[bt].z, Bf[bt].w);
            }

        MB_ARRIVE(sb + s * 16 + 8);
    }

    __syncthreads();   // protect mbarriers/stages before C overlay

    // ---- epilogue: frags -> C[128][129] fp32, then fused neuron math ----
    float* C = (float*)smem;
#pragma unroll
    for (int mt = 0; mt < 4; mt++)
#pragma unroll
        for (int nt = 0; nt < 4; nt++) {
            const int r  = wm * 64 + mt * 16 + (lane >> 2);
            const int cc = wn * 32 + nt * 8 + (lane & 3) * 2;
            C[r * C_STRIDE + cc]           = acc[mt][nt][0];
            C[r * C_STRIDE + cc + 1]       = acc[mt][nt][1];
            C[(r + 8) * C_STRIDE + cc]     = acc[mt][nt][2];
            C[(r + 8) * C_STRIDE + cc + 1] = acc[mt][nt][3];
        }
    __syncthreads();

    // 2 threads per o-row: (row, half h of ds)
    const int row = tid & 127;
    const int h   = tid >> 7;
    const int o   = o0 + row;
    float td[4] = {0.f, 0.f, 0.f, 0.f};
    const float4* w4 = (const float4*)(w_syn + (size_t)o * 128 + h * 64);
#pragma unroll
    for (int j4 = 0; j4 < 16; j4++) {
        const float4 w = w4[j4];
        const int e = h * 64 + j4 * 4;
        td[j4 >> 2] += C[row * C_STRIDE + e]     * w.x
                     + C[row * C_STRIDE + e + 1] * w.y
                     + C[row * C_STRIDE + e + 2] * w.z
                     + C[row * C_STRIDE + e + 3] * w.w;
    }
    float sh = 0.f;
#pragma unroll
    for (int d = 0; d < 4; d++) {
        const int dd = h * 4 + d;
        sh += tanhf(td[d] + b_dend[o * 8 + dd]) * w_dend[o * 8 + dd];
    }
    float* spart = (float*)(smem + 128 * C_STRIDE * 4);
    spart[h * 128 + row] = sh;
    __syncthreads();
    if (tid < 128) {
        const float s = spart[tid] + spart[128 + tid] + b_soma[o0 + tid];
        out[b * NN + o0 + tid] = 1.0f / (1.0f + expf(-s));
    }
}

// ---------------------------------------------------------------------------
extern "C" void kernel_launch(void* const* d_in, const int* in_sizes, int n_in,
                              void* d_out, int out_size)
{
    const float* x      = (const float*)d_in[0];   // [B, N, D, S]
    const float* M      = (const float*)d_in[1];   // [N, N]
    const float* w_syn  = (const float*)d_in[2];   // [N, D, S]
    const float* b_dend = (const float*)d_in[3];   // [N, D]
    const float* w_dend = (const float*)d_in[4];   // [N, D]
    const float* b_soma = (const float*)d_in[5];   // [N]
    float* out          = (float*)d_out;           // [B, N]

    cudaFuncSetAttribute(gemm_neuron, cudaFuncAttributeMaxDynamicSharedMemorySize, SMEM_REQ);

    prep<<<dim3(64, 64), 256>>>(x, M);
    gemm_neuron<<<dim3(NN / 128, BB), 256, SMEM_REQ>>>(w_syn, b_dend, w_dend, b_soma, out);
}

// round 13
// speedup vs baseline: 1.0224x; 1.0224x over previous
#include <cuda_runtime.h>
#include <cuda_fp16.h>
#include <math.h>
#include <stdint.h>

// Problem constants: B=64, N=1024, D=8, S=16 -> DS=128, K=1024
#define NN    1024
#define BB    64
#define DS    128
#define KDIM  1024
#define NKB   (KDIM / 16)            // 64 k16-blocks
#define NSTG  8                      // pipeline stages
#define STGB  8192                   // bytes per stage: A 4KB + B 4KB (frag order)
#define C_STRIDE 129
#define SMEM_REQ (128 * C_STRIDE * 4 + 1024)   // 67072 (covers 1024 + 8*8192 = 66560)

__device__ __forceinline__ uint32_t smem_u32(const void* p) {
    uint32_t a;
    asm("{ .reg .u64 t; cvta.to.shared.u64 t, %1; cvt.u32.u64 %0, t; }" : "=r"(a) : "l"(p));
    return a;
}
__device__ __forceinline__ void cp16(uint32_t dst, const void* src) {
    asm volatile("cp.async.cg.shared.global [%0], [%1], 16;" :: "r"(dst), "l"(src) : "memory");
}
__device__ __forceinline__ void mma16816(float* c, const uint32_t* a, uint32_t b0, uint32_t b1) {
    asm volatile("mma.sync.aligned.m16n8k16.row.col.f32.f16.f16.f32 "
                 "{%0,%1,%2,%3}, {%4,%5,%6,%7}, {%8,%9}, {%0,%1,%2,%3};"
                 : "+f"(c[0]), "+f"(c[1]), "+f"(c[2]), "+f"(c[3])
                 : "r"(a[0]), "r"(a[1]), "r"(a[2]), "r"(a[3]), "r"(b0), "r"(b1));
}

#define MB_INIT(mbar, cnt) \
    asm volatile("mbarrier.init.shared.b64 [%0], %1;" :: "r"(mbar), "r"((uint32_t)(cnt)) : "memory")
#define MB_ARRIVE(mbar) \
    asm volatile("mbarrier.arrive.shared.b64 _, [%0];" :: "r"(mbar) : "memory")
// .noinc is load-bearing: without it each call bumps the pending count first
// (net-zero progress) and the barrier never completes (R11 deadlock).
#define CP_MB_ARRIVE(mbar) \
    asm volatile("cp.async.mbarrier.arrive.noinc.shared::cta.b64 [%0];" :: "r"(mbar) : "memory")
#define MB_WAIT(mbar, par) do {                                                \
    uint32_t _m = (mbar); uint32_t _p = (uint32_t)(par);                       \
    asm volatile("{\n\t.reg .pred P1;\n\t"                                     \
        "WL_%=:\n\t"                                                           \
        "mbarrier.try_wait.parity.acquire.cta.shared::cta.b64 P1, [%0], %1, 0x989680;\n\t" \
        "@P1 bra.uni WD_%=;\n\t"                                               \
        "bra.uni WL_%=;\n\t"                                                   \
        "WD_%=:\n\t}"                                                          \
        :: "r"(_m), "r"(_p) : "memory");                                       \
} while (0)

// ---------------- device scratch: FRAGMENT-ORDERED operands ----------------
// A frags: [row16 0..63][kb 0..63][lane 0..31][4 u32]   (2 MB)
// B frags: [b*8 + n16][kb][lane][4 u32]                (16 MB)
__device__ uint32_t g_Af[64 * NKB * 128];
__device__ uint32_t g_Xf[BB * 8 * NKB * 128];

// ---------------- prep: build fragment-ordered A and B (proven R10) --------
__global__ void prep(const float* __restrict__ x, const float* __restrict__ M)
{
    const int tid = threadIdx.x;
    const int kb  = blockIdx.x;

    if (tid < 128) {
        const int row16 = blockIdx.y;
        const int lane = tid >> 2, reg = tid & 3;
        const int R = row16 * 16 + (lane >> 2) + (reg & 1) * 8;
        const int C = kb * 16 + (lane & 3) * 2 + ((reg >> 1) & 1) * 8;
        const float2 mv = *(const float2*)&M[(size_t)R * NN + C];
        const __half2 h = __floats2half2_rn(mv.x, mv.y);
        g_Af[((size_t)row16 * NKB + kb) * 128 + tid] = *(const uint32_t*)&h;
    }

    __shared__ float sx[16 * 132];
    const int b = blockIdx.y;
    const float* src = x + ((size_t)b * NN + kb * 16) * DS;
#pragma unroll
    for (int j = tid; j < 16 * 128; j += 256) {
        const int r = j >> 7, c = j & 127;
        sx[r * 132 + c] = src[r * DS + c];
    }
    __syncthreads();

    uint32_t* dstB = g_Xf + ((size_t)(b * 8) * NKB + kb) * 128;
#pragma unroll
    for (int it = 0; it < 4; it++) {
        const int u = it * 256 + tid;
        const int n16 = u >> 7, tt = u & 127;
        const int lane = tt >> 2, reg = tt & 3;
        const int n  = n16 * 16 + (lane >> 2) + ((reg >> 1) & 1) * 8;
        const int k0 = (lane & 3) * 2 + (reg & 1) * 8;
        const __half2 h = __floats2half2_rn(sx[k0 * 132 + n], sx[(k0 + 1) * 132 + n]);
        dstB[(size_t)n16 * (NKB * 128) + tt] = *(const uint32_t*)&h;
    }
}

// ---------------- GEMM: 8-stage mbarrier cp.async pipeline -----------------
// Grid (8, 64). Block 256 = 8 warps (2 m x 4 n), warp m64n32.
// smem: [0:128) mbarriers (full[s]@s*16, empty[s]@s*16+8); stages at 1024.
// empty[s] counts WARPS (8), arrived by lane 0 only — per-thread arrives on
// one smem address serialize at ATOMS rates (~8us/launch, R12 lesson).
__global__ void __launch_bounds__(256, 2) gemm_neuron(
    const float* __restrict__ w_syn,    // [N, 128]
    const float* __restrict__ b_dend,   // [N, 8]
    const float* __restrict__ w_dend,   // [N, 8]
    const float* __restrict__ b_soma,   // [N]
    float* __restrict__ out)            // [B, N]
{
    extern __shared__ char smem[];
    const uint32_t sb = smem_u32(smem);
    const int tid  = threadIdx.x;
    const int wid  = tid >> 5, lane = tid & 31;
    const int wm   = wid & 1;           // m-warp: 64 rows
    const int wn   = wid >> 1;          // n-warp: 32 cols
    const int o0   = blockIdx.x * 128;
    const int b    = blockIdx.y;

    if (tid == 0) {
#pragma unroll
        for (int s = 0; s < NSTG; s++) {
            MB_INIT(sb + s * 16,     256);   // full: 256 cp.async noinc arrivals
            MB_INIT(sb + s * 16 + 8, 8);     // empty: one arrive per warp
        }
    }
    __syncthreads();

    // staging role: threads 0..127 -> A tile (tt>>4), 128..255 -> B tile
    const int  isA = (tid < 128);
    const int  tt  = isA ? tid : tid - 128;
    const int  tile = isA ? (blockIdx.x * 8 + (tt >> 4)) : (b * 8 + (tt >> 4));
    const uint32_t* srcbase = (isA ? g_Af : g_Xf)
                            + ((size_t)tile * NKB) * 128 + (tt & 15) * 8;
    const uint32_t dstoff = 1024 + (isA ? 0 : 4096) + (tt >> 4) * 512 + (tt & 15) * 32;

#define STAGE(j, dowait) do {                                              \
    const int _s = (j) & (NSTG - 1);                                       \
    if (dowait) MB_WAIT(sb + _s * 16 + 8, (((j) >> 3) + 1) & 1);           \
    const uint32_t _d = sb + dstoff + _s * STGB;                           \
    const uint32_t* _src = srcbase + (size_t)(j) * 128;                    \
    cp16(_d,      _src);                                                   \
    cp16(_d + 16, _src + 4);                                               \
    CP_MB_ARRIVE(sb + _s * 16);                                            \
} while (0)

    // prologue: fill 7 stages (no waits needed, buffers virgin)
#pragma unroll
    for (int j = 0; j < NSTG - 1; j++) STAGE(j, false);

    float acc[4][4][4];
#pragma unroll
    for (int mt = 0; mt < 4; mt++)
#pragma unroll
        for (int nt = 0; nt < 4; nt++)
#pragma unroll
            for (int q = 0; q < 4; q++) acc[mt][nt][q] = 0.f;

    const uint32_t aoff = 1024 + wm * 4 * 512 + lane * 16;
    const uint32_t boff = 1024 + 4096 + wn * 2 * 512 + lane * 16;

#pragma unroll 2
    for (int kb = 0; kb < NKB; kb++) {
        if (kb + NSTG - 1 < NKB) STAGE(kb + NSTG - 1, true);

        const int s = kb & (NSTG - 1);
        MB_WAIT(sb + s * 16, (kb >> 3) & 1);

        const char* stg = smem + s * STGB;
        uint4 Af[4], Bf[2];
#pragma unroll
        for (int mt = 0; mt < 4; mt++)
            Af[mt] = *(const uint4*)(stg + aoff + mt * 512);
#pragma unroll
        for (int bt = 0; bt < 2; bt++)
            Bf[bt] = *(const uint4*)(stg + boff + bt * 512);

#pragma unroll
        for (int mt = 0; mt < 4; mt++)
#pragma unroll
            for (int bt = 0; bt < 2; bt++) {
                mma16816(acc[mt][bt * 2],     (const uint32_t*)&Af[mt], Bf[bt].x, Bf[bt].y);
                mma16816(acc[mt][bt * 2 + 1], (const uint32_t*)&Af[mt], Bf[bt].z, Bf[bt].w);
            }

        // warp-converged after mma.sync: one empty-arrive per warp
        if (lane == 0) MB_ARRIVE(sb + s * 16 + 8);
    }

    __syncthreads();   // protect mbarriers/stages before C overlay

    // ---- epilogue: frags -> C[128][129] fp32, then fused neuron math ----
    float* C = (float*)smem;
#pragma unroll
    for (int mt = 0; mt < 4; mt++)
#pragma unroll
        for (int nt = 0; nt < 4; nt++) {
            const int r  = wm * 64 + mt * 16 + (lane >> 2);
            const int cc = wn * 32 + nt * 8 + (lane & 3) * 2;
            C[r * C_STRIDE + cc]           = acc[mt][nt][0];
            C[r * C_STRIDE + cc + 1]       = acc[mt][nt][1];
            C[(r + 8) * C_STRIDE + cc]     = acc[mt][nt][2];
            C[(r + 8) * C_STRIDE + cc + 1] = acc[mt][nt][3];
        }
    __syncthreads();

    // 2 threads per o-row: (row, half h of ds)
    const int row = tid & 127;
    const int h   = tid >> 7;
    const int o   = o0 + row;
    float td[4] = {0.f, 0.f, 0.f, 0.f};
    const float4* w4 = (const float4*)(w_syn + (size_t)o * 128 + h * 64);
#pragma unroll
    for (int j4 = 0; j4 < 16; j4++) {
        const float4 w = w4[j4];
        const int e = h * 64 + j4 * 4;
        td[j4 >> 2] += C[row * C_STRIDE + e]     * w.x
                     + C[row * C_STRIDE + e + 1] * w.y
                     + C[row * C_STRIDE + e + 2] * w.z
                     + C[row * C_STRIDE + e + 3] * w.w;
    }
    float sh = 0.f;
#pragma unroll
    for (int d = 0; d < 4; d++) {
        const int dd = h * 4 + d;
        sh += tanhf(td[d] + b_dend[o * 8 + dd]) * w_dend[o * 8 + dd];
    }
    float* spart = (float*)(smem + 128 * C_STRIDE * 4);
    spart[h * 128 + row] = sh;
    __syncthreads();
    if (tid < 128) {
        const float s = spart[tid] + spart[128 + tid] + b_soma[o0 + tid];
        out[b * NN + o0 + tid] = 1.0f / (1.0f + expf(-s));
    }
}

// ---------------------------------------------------------------------------
extern "C" void kernel_launch(void* const* d_in, const int* in_sizes, int n_in,
                              void* d_out, int out_size)
{
    const float* x      = (const float*)d_in[0];   // [B, N, D, S]
    const float* M      = (const float*)d_in[1];   // [N, N]
    const float* w_syn  = (const float*)d_in[2];   // [N, D, S]
    const float* b_dend = (const float*)d_in[3];   // [N, D]
    const float* w_dend = (const float*)d_in[4];   // [N, D]
    const float* b_soma = (const float*)d_in[5];   // [N]
    float* out          = (float*)d_out;           // [B, N]

    cudaFuncSetAttribute(gemm_neuron, cudaFuncAttributeMaxDynamicSharedMemorySize, SMEM_REQ);

    prep<<<dim3(64, 64), 256>>>(x, M);
    gemm_neuron<<<dim3(NN / 128, BB), 256, SMEM_REQ>>>(w_syn, b_dend, w_dend, b_soma, out);
}